// round 1
// baseline (speedup 1.0000x reference)
#include <cuda_runtime.h>
#include <math.h>

#define N_PTS 20000
#define M_PTS 160000
#define CI 128
#define CO 64
#define GD 34
#define GSZ (GD*GD*GD)

// ---------------- device scratch (no allocs allowed) ----------------
__device__ int   g_pgrid[GSZ];            // parent index grid, padded [-1..32] per axis
__device__ float g_h[N_PTS*CI];           // silu(gn1(x)) per parent
__device__ float g_skip[N_PTS*CO];        // x_feats @ Ws + bs per parent
__device__ float g_mid[M_PTS*CO];         // conv1 output per child
__device__ float g_act[M_PTS*CO];         // silu(gn2(mid))
__device__ float g_weff[8*8*CI*CO];       // folded conv1 weights [o][n][cin][cout]
__device__ float g_sum1[CI], g_sq1[CI], g_mu1[32], g_rs1[32];
__device__ float g_sum2[CO], g_sq2[CO], g_mu2[32], g_rs2[32];

// ---------------- small kernels ----------------
__global__ void k_init(){
    int i = blockIdx.x*256 + threadIdx.x;
    if (i < GSZ) g_pgrid[i] = -1;
    if (i < CI){ g_sum1[i]=0.f; g_sq1[i]=0.f; }
    if (i < CO){ g_sum2[i]=0.f; g_sq2[i]=0.f; }
}

__global__ void k_scatter(const int* __restrict__ coords){
    int p = blockIdx.x*256 + threadIdx.x;
    if (p < N_PTS){
        int x=coords[p*4+1], y=coords[p*4+2], z=coords[p*4+3];
        g_pgrid[((x+1)*GD + (y+1))*GD + (z+1)] = p;
    }
}

__global__ void k_stats1(const float* __restrict__ xf){
    int c = threadIdx.x;            // 128 threads = channels
    float s=0.f, s2=0.f;
    for (int r = blockIdx.x; r < N_PTS; r += gridDim.x){
        float v = xf[r*CI + c]; s += v; s2 += v*v;
    }
    atomicAdd(&g_sum1[c], s); atomicAdd(&g_sq1[c], s2);
}

__global__ void k_fin1(){
    int g = threadIdx.x;
    if (g < 32){
        float s=0.f, s2=0.f;
        for (int j=0;j<4;j++){ s += g_sum1[g*4+j]; s2 += g_sq1[g*4+j]; }
        float inv = 1.f/(float)(N_PTS*4);
        float mu = s*inv;
        float var = s2*inv - mu*mu;
        g_mu1[g] = mu; g_rs1[g] = rsqrtf(var + 1e-5f);
    }
}

__global__ void k_h(const float* __restrict__ xf,
                    const float* __restrict__ gma, const float* __restrict__ bta){
    int i = blockIdx.x*256 + threadIdx.x;     // exact: N_PTS*CI multiple of 256
    int c = i & (CI-1); int g = c >> 2;
    float v = (xf[i] - g_mu1[g])*g_rs1[g]*gma[c] + bta[c];
    g_h[i] = v / (1.f + expf(-v));
}

// Fold 27 child-level taps into 8 parent-level neighbor matrices per child parity o.
__global__ void k_weff(const float* __restrict__ W1){
    int idx = blockIdx.x*256 + threadIdx.x;   // 8*8*128*64 = 524288 exact
    int cout = idx & 63, cin = (idx>>6)&127, n = (idx>>13)&7, o = idx>>16;
    int d0=(o>>2)&1, d1=(o>>1)&1, d2=o&1;
    int n0=(n>>2)&1, n1=(n>>1)&1, n2=n&1;
    float s = 0.f;
    for (int i=0;i<3;i++){
        int t0=d0+i-1; int p0=(t0>=2)?1:((t0>=0)?0:-1);
        if (p0 - d0 + 1 != n0) continue;
        for (int j=0;j<3;j++){
            int t1=d1+j-1; int p1=(t1>=2)?1:((t1>=0)?0:-1);
            if (p1 - d1 + 1 != n1) continue;
            for (int k=0;k<3;k++){
                int t2=d2+k-1; int p2=(t2>=2)?1:((t2>=0)?0:-1);
                if (p2 - d2 + 1 != n2) continue;
                s += W1[(((i*3+j)*3+k)*CI + cin)*CO + cout];
            }
        }
    }
    g_weff[idx] = s;
}

// ---------------- register-tile FMA helper ----------------
__device__ __forceinline__ void mma_row(float4 a, float4 w0, float4 w1, float4 w2, float4 w3,
                                        float acc[4]){
    acc[0]=fmaf(a.x,w0.x,acc[0]); acc[0]=fmaf(a.y,w1.x,acc[0]); acc[0]=fmaf(a.z,w2.x,acc[0]); acc[0]=fmaf(a.w,w3.x,acc[0]);
    acc[1]=fmaf(a.x,w0.y,acc[1]); acc[1]=fmaf(a.y,w1.y,acc[1]); acc[1]=fmaf(a.z,w2.y,acc[1]); acc[1]=fmaf(a.w,w3.y,acc[1]);
    acc[2]=fmaf(a.x,w0.z,acc[2]); acc[2]=fmaf(a.y,w1.z,acc[2]); acc[2]=fmaf(a.z,w2.z,acc[2]); acc[2]=fmaf(a.w,w3.z,acc[2]);
    acc[3]=fmaf(a.x,w0.w,acc[3]); acc[3]=fmaf(a.y,w1.w,acc[3]); acc[3]=fmaf(a.z,w2.w,acc[3]); acc[3]=fmaf(a.w,w3.w,acc[3]);
}

// ---------------- skip GEMM: 20000x128 @ 128x64 ----------------
__global__ __launch_bounds__(256) void k_skip(const float* __restrict__ xf,
                                              const float* __restrict__ Ws,
                                              const float* __restrict__ bs){
    __shared__ float A_s[64][68];
    __shared__ float W_s[64][68];
    int t = threadIdx.x;
    int p0 = blockIdx.x*64;
    float acc[4][4] = {};
    int tr = t>>4, tc = t&15;
    for (int ck = 0; ck < 2; ck++){
        __syncthreads();
        #pragma unroll
        for (int rep = 0; rep < 4; rep++){
            int idx = rep*256 + t;
            int r = idx>>4, kv = idx&15;
            int p = p0 + r;
            float4 v = make_float4(0.f,0.f,0.f,0.f);
            if (p < N_PTS) v = *(const float4*)&xf[p*CI + ck*64 + kv*4];
            *(float4*)&A_s[r][kv*4] = v;
            *(float4*)&W_s[r][kv*4] = *(const float4*)&Ws[(ck*64 + r)*CO + kv*4];
        }
        __syncthreads();
        #pragma unroll
        for (int kk = 0; kk < 64; kk += 4){
            float4 w0 = *(float4*)&W_s[kk+0][tc*4];
            float4 w1 = *(float4*)&W_s[kk+1][tc*4];
            float4 w2 = *(float4*)&W_s[kk+2][tc*4];
            float4 w3 = *(float4*)&W_s[kk+3][tc*4];
            #pragma unroll
            for (int i = 0; i < 4; i++){
                float4 a = *(float4*)&A_s[tr*4+i][kk];
                mma_row(a, w0, w1, w2, w3, acc[i]);
            }
        }
    }
    #pragma unroll
    for (int i = 0; i < 4; i++){
        int p = p0 + tr*4 + i;
        if (p < N_PTS){
            float4 r;
            r.x = acc[i][0] + bs[tc*4+0];
            r.y = acc[i][1] + bs[tc*4+1];
            r.z = acc[i][2] + bs[tc*4+2];
            r.w = acc[i][3] + bs[tc*4+3];
            *(float4*)&g_skip[p*CO + tc*4] = r;
        }
    }
}

// ---------------- conv1: per child parity o, 8 parent neighbors, folded weights ----------------
__global__ __launch_bounds__(256) void k_conv1(const int* __restrict__ coords,
                                               const float* __restrict__ b1){
    __shared__ float A_s[64][68];
    __shared__ float W_s[64][68];
    __shared__ int   q_s[64][8];
    int t = threadIdx.x;
    int p0 = blockIdx.x*64;
    int o  = blockIdx.y;
    int dx=(o>>2)&1, dy=(o>>1)&1, dz=o&1;
    for (int e = t; e < 512; e += 256){
        int r = e>>3, n = e&7;
        int p = p0 + r; int q = -1;
        if (p < N_PTS){
            int x=coords[p*4+1], y=coords[p*4+2], z=coords[p*4+3];
            int ox = dx-1+((n>>2)&1), oy = dy-1+((n>>1)&1), oz = dz-1+(n&1);
            q = g_pgrid[((x+ox+1)*GD + (y+oy+1))*GD + (z+oz+1)];
        }
        q_s[r][n] = q;
    }
    float acc[4][4] = {};
    int tr = t>>4, tc = t&15;
    for (int n = 0; n < 8; n++){
        const float* Wn = g_weff + (o*8 + n)*CI*CO;
        for (int ck = 0; ck < 2; ck++){
            __syncthreads();
            #pragma unroll
            for (int rep = 0; rep < 4; rep++){
                int idx = rep*256 + t;
                int r = idx>>4, kv = idx&15;
                int q = q_s[r][n];
                float4 v = make_float4(0.f,0.f,0.f,0.f);
                if (q >= 0) v = *(const float4*)&g_h[q*CI + ck*64 + kv*4];
                *(float4*)&A_s[r][kv*4] = v;
                *(float4*)&W_s[r][kv*4] = *(const float4*)&Wn[(ck*64 + r)*CO + kv*4];
            }
            __syncthreads();
            #pragma unroll
            for (int kk = 0; kk < 64; kk += 4){
                float4 w0 = *(float4*)&W_s[kk+0][tc*4];
                float4 w1 = *(float4*)&W_s[kk+1][tc*4];
                float4 w2 = *(float4*)&W_s[kk+2][tc*4];
                float4 w3 = *(float4*)&W_s[kk+3][tc*4];
                #pragma unroll
                for (int i = 0; i < 4; i++){
                    float4 a = *(float4*)&A_s[tr*4+i][kk];
                    mma_row(a, w0, w1, w2, w3, acc[i]);
                }
            }
        }
    }
    #pragma unroll
    for (int i = 0; i < 4; i++){
        int p = p0 + tr*4 + i;
        if (p < N_PTS){
            float4 r;
            r.x = acc[i][0] + b1[tc*4+0];
            r.y = acc[i][1] + b1[tc*4+1];
            r.z = acc[i][2] + b1[tc*4+2];
            r.w = acc[i][3] + b1[tc*4+3];
            *(float4*)&g_mid[(p*8 + o)*CO + tc*4] = r;
        }
    }
}

__global__ void k_stats2(){
    __shared__ float ss[256], ss2[256];
    int t = threadIdx.x; int c = t&63; int lane = t>>6;
    float s=0.f, s2=0.f;
    for (int r = blockIdx.x*4 + lane; r < M_PTS; r += gridDim.x*4){
        float v = g_mid[r*CO + c]; s += v; s2 += v*v;
    }
    ss[t]=s; ss2[t]=s2; __syncthreads();
    if (t < 64){
        float a = ss[t]+ss[t+64]+ss[t+128]+ss[t+192];
        float b = ss2[t]+ss2[t+64]+ss2[t+128]+ss2[t+192];
        atomicAdd(&g_sum2[c], a); atomicAdd(&g_sq2[c], b);
    }
}

__global__ void k_fin2(){
    int g = threadIdx.x;
    if (g < 32){
        float s  = g_sum2[2*g] + g_sum2[2*g+1];
        float s2 = g_sq2[2*g]  + g_sq2[2*g+1];
        float inv = 1.f/(float)(M_PTS*2);
        float mu = s*inv;
        float var = s2*inv - mu*mu;
        g_mu2[g] = mu; g_rs2[g] = rsqrtf(var + 1e-5f);
    }
}

__global__ void k_act(const float* __restrict__ gma, const float* __restrict__ bta){
    int i = blockIdx.x*256 + threadIdx.x;     // exact: M_PTS*CO multiple of 256
    int c = i & 63; int g = c >> 1;
    float v = (g_mid[i] - g_mu2[g])*g_rs2[g]*gma[c] + bta[c];
    g_act[i] = v / (1.f + expf(-v));
}

// ---------------- conv2: 27 child-level taps, 64->64, + bias + skip ----------------
__global__ __launch_bounds__(256) void k_conv2(const int* __restrict__ coords,
                                               const float* __restrict__ W2,
                                               const float* __restrict__ b2,
                                               float* __restrict__ out){
    __shared__ float A_s[64][68];
    __shared__ float W_s[64][68];
    __shared__ int   nbr_s[64][27];
    int t = threadIdx.x;
    int m0 = blockIdx.x*64;                   // M_PTS/64 = 2500 exact
    for (int e = t; e < 64*27; e += 256){
        int r = e/27, tap = e - r*27;
        int m = m0 + r, p = m>>3, o = m&7;
        int x=coords[p*4+1], y=coords[p*4+2], z=coords[p*4+3];
        int cx = 2*x + ((o>>2)&1) + tap/9 - 1;
        int cy = 2*y + ((o>>1)&1) + (tap/3)%3 - 1;
        int cz = 2*z + (o&1) + tap%3 - 1;
        int q = g_pgrid[(((cx>>1)+1)*GD + ((cy>>1)+1))*GD + ((cz>>1)+1)];
        nbr_s[r][tap] = (q >= 0) ? (q*8 + ((cx&1)<<2) + ((cy&1)<<1) + (cz&1)) : -1;
    }
    float acc[4][4] = {};
    int tr = t>>4, tc = t&15;
    for (int tap = 0; tap < 27; tap++){
        __syncthreads();
        #pragma unroll
        for (int rep = 0; rep < 4; rep++){
            int idx = rep*256 + t;
            int r = idx>>4, kv = idx&15;
            int nb = nbr_s[r][tap];
            float4 v = make_float4(0.f,0.f,0.f,0.f);
            if (nb >= 0) v = *(const float4*)&g_act[nb*CO + kv*4];
            *(float4*)&A_s[r][kv*4] = v;
            *(float4*)&W_s[r][kv*4] = *(const float4*)&W2[(tap*CO + r)*CO + kv*4];
        }
        __syncthreads();
        #pragma unroll
        for (int kk = 0; kk < 64; kk += 4){
            float4 w0 = *(float4*)&W_s[kk+0][tc*4];
            float4 w1 = *(float4*)&W_s[kk+1][tc*4];
            float4 w2 = *(float4*)&W_s[kk+2][tc*4];
            float4 w3 = *(float4*)&W_s[kk+3][tc*4];
            #pragma unroll
            for (int i = 0; i < 4; i++){
                float4 a = *(float4*)&A_s[tr*4+i][kk];
                mma_row(a, w0, w1, w2, w3, acc[i]);
            }
        }
    }
    #pragma unroll
    for (int i = 0; i < 4; i++){
        int m = m0 + tr*4 + i;
        int p = m >> 3;
        float4 r;
        r.x = acc[i][0] + b2[tc*4+0] + g_skip[p*CO + tc*4+0];
        r.y = acc[i][1] + b2[tc*4+1] + g_skip[p*CO + tc*4+1];
        r.z = acc[i][2] + b2[tc*4+2] + g_skip[p*CO + tc*4+2];
        r.w = acc[i][3] + b2[tc*4+3] + g_skip[p*CO + tc*4+3];
        *(float4*)&out[m*CO + tc*4] = r;
    }
}

// ---------------- launch ----------------
extern "C" void kernel_launch(void* const* d_in, const int* in_sizes, int n_in,
                              void* d_out, int out_size){
    const float* xf    = (const float*)d_in[0];
    const int*   coords= (const int*)  d_in[1];
    const float* gn1g  = (const float*)d_in[2];
    const float* gn1b  = (const float*)d_in[3];
    const float* W1    = (const float*)d_in[4];
    const float* b1    = (const float*)d_in[5];
    const float* gn2g  = (const float*)d_in[6];
    const float* gn2b  = (const float*)d_in[7];
    const float* W2    = (const float*)d_in[8];
    const float* b2    = (const float*)d_in[9];
    const float* Ws    = (const float*)d_in[10];
    const float* bs    = (const float*)d_in[11];
    float* out = (float*)d_out;

    k_init<<<(GSZ+255)/256, 256>>>();
    k_scatter<<<(N_PTS+255)/256, 256>>>(coords);
    k_stats1<<<160, 128>>>(xf);
    k_fin1<<<1, 32>>>();
    k_h<<<N_PTS*CI/256, 256>>>(xf, gn1g, gn1b);
    k_weff<<<8*8*CI*CO/256, 256>>>(W1);
    k_skip<<<(N_PTS+63)/64, 256>>>(xf, Ws, bs);
    k_conv1<<<dim3((N_PTS+63)/64, 8), 256>>>(coords, b1);
    k_stats2<<<400, 256>>>();
    k_fin2<<<1, 32>>>();
    k_act<<<M_PTS*CO/256, 256>>>(gn2g, gn2b);
    k_conv2<<<M_PTS/64, 256>>>(coords, W2, b2, out);
}